// round 1
// baseline (speedup 1.0000x reference)
#include <cuda_runtime.h>
#include <math.h>

#define Bn 16
#define Hn 512
#define Wn 512
#define HW (Hn*Wn)
#define NBLK 64          // 512/8 blocks per dim
#define BLKS_PER_IMG 1024  // K1: (512/32)*(512/8)

// ---------------- scratch (device globals; no allocation allowed) ----------
__device__ unsigned char g_code[(size_t)Bn*HW];     // LBP code 0..9
__device__ float g_partial[Bn*BLKS_PER_IMG*3];      // per-block rgb sums
__device__ int   g_maxcode[Bn];
__device__ float g_scale[Bn*3];
__device__ float g_invmx[Bn];
__device__ float g_strength[Bn*NBLK*NBLK];

// DCT basis rows 4 and 3 (orthonormal DCT-II, scale sqrt(2/8)=0.5)
__constant__ float c_d4[8] = { 0.35355339f,-0.35355339f,-0.35355339f, 0.35355339f,
                               0.35355339f,-0.35355339f,-0.35355339f, 0.35355339f };
__constant__ float c_d3[8] = { 0.41573481f,-0.09754516f,-0.49039264f,-0.27778512f,
                               0.27778512f, 0.49039264f, 0.09754516f,-0.41573481f };

__global__ void k_init() {
    if (threadIdx.x < Bn) g_maxcode[threadIdx.x] = 0;
}

// ---------------- K1: gray + LBP + rgb partial sums + code max -------------
// block (32,8), grid (16, 64, B)
__global__ void k_lbp(const float* __restrict__ frame) {
    __shared__ float gs[10][34];
    const int b = blockIdx.z;
    const float* fr = frame + (size_t)b*3*HW;
    const int bx0 = blockIdx.x*32, by0 = blockIdx.y*8;
    const int tx = threadIdx.x, ty = threadIdx.y;
    const int tid = ty*32 + tx;

    for (int i = tid; i < 340; i += 256) {
        int sy = i / 34, sx = i % 34;
        int y = min(max(by0 + sy - 1, 0), Hn-1);
        int x = min(max(bx0 + sx - 1, 0), Wn-1);
        int o = y*Wn + x;
        gs[sy][sx] = 0.299f*fr[o] + 0.587f*fr[HW+o] + 0.114f*fr[2*HW+o];
    }
    __syncthreads();

    const int x = bx0 + tx, y = by0 + ty;
    const float g0 = gs[ty+1][tx+1];
    // neighbor order: (-1,0),(-1,1),(0,1),(1,1),(1,0),(1,-1),(0,-1),(-1,-1)
    int bb0 = gs[ty  ][tx+1] >= g0;
    int bb1 = gs[ty  ][tx+2] >= g0;
    int bb2 = gs[ty+1][tx+2] >= g0;
    int bb3 = gs[ty+2][tx+2] >= g0;
    int bb4 = gs[ty+2][tx+1] >= g0;
    int bb5 = gs[ty+2][tx  ] >= g0;
    int bb6 = gs[ty+1][tx  ] >= g0;
    int bb7 = gs[ty  ][tx  ] >= g0;
    int s = bb0+bb1+bb2+bb3+bb4+bb5+bb6+bb7;
    int trans = abs(bb0-bb7)+abs(bb1-bb0)+abs(bb2-bb1)+abs(bb3-bb2)
              + abs(bb4-bb3)+abs(bb5-bb4)+abs(bb6-bb5)+abs(bb7-bb6);
    int code = (trans <= 2) ? s : 9;
    g_code[(size_t)b*HW + y*Wn + x] = (unsigned char)code;

    // rgb sums for channel attention (own pixel; L1/L2 hit from halo load)
    int o = y*Wn + x;
    float r = fr[o], g = fr[HW+o], bl = fr[2*HW+o];
    int m = code;
    #pragma unroll
    for (int off = 16; off; off >>= 1) {
        r  += __shfl_down_sync(0xffffffffu, r,  off);
        g  += __shfl_down_sync(0xffffffffu, g,  off);
        bl += __shfl_down_sync(0xffffffffu, bl, off);
        m = max(m, __shfl_down_sync(0xffffffffu, m, off));
    }
    __shared__ float rs[3][8];
    __shared__ int ms[8];
    int lane = tid & 31, warp = tid >> 5;
    if (lane == 0) { rs[0][warp] = r; rs[1][warp] = g; rs[2][warp] = bl; ms[warp] = m; }
    __syncthreads();
    if (tid == 0) {
        float R=0, G=0, Bs=0; int mm = 0;
        #pragma unroll
        for (int w = 0; w < 8; w++) { R += rs[0][w]; G += rs[1][w]; Bs += rs[2][w]; mm = max(mm, ms[w]); }
        int gbid = b*BLKS_PER_IMG + blockIdx.y*16 + blockIdx.x;
        g_partial[gbid*3+0] = R;
        g_partial[gbid*3+1] = G;
        g_partial[gbid*3+2] = Bs;
        atomicMax(&g_maxcode[b], mm);
    }
}

// ---------------- K2: channel attention scale + 1/max ----------------------
// grid (B), block 256
__global__ void k_scale(const float* __restrict__ ca_w1, const float* __restrict__ ca_w2) {
    const int b = blockIdx.x;
    const int t = threadIdx.x;
    float r = 0.f, g = 0.f, bl = 0.f;
    for (int i = t; i < BLKS_PER_IMG; i += 256) {
        int o = (b*BLKS_PER_IMG + i)*3;
        r += g_partial[o]; g += g_partial[o+1]; bl += g_partial[o+2];
    }
    __shared__ float sm[3][256];
    sm[0][t] = r; sm[1][t] = g; sm[2][t] = bl;
    __syncthreads();
    for (int off = 128; off; off >>= 1) {
        if (t < off) { sm[0][t] += sm[0][t+off]; sm[1][t] += sm[1][t+off]; sm[2][t] += sm[2][t+off]; }
        __syncthreads();
    }
    if (t == 0) {
        const float inv = 1.0f / (float)HW;
        float rm = sm[0][0]*inv, gm = sm[1][0]*inv, bm = sm[2][0]*inv;
        float p0 =  0.299f*rm + 0.587f*gm + 0.114f*bm;
        float p1 = -0.147f*rm - 0.289f*gm + 0.436f*bm;
        float p2 =  0.615f*rm - 0.515f*gm - 0.100f*bm;
        float h0 = fmaxf(p0*ca_w1[0] + p1*ca_w1[1] + p2*ca_w1[2], 0.f);
        float h1 = fmaxf(p0*ca_w1[3] + p1*ca_w1[4] + p2*ca_w1[5], 0.f);
        float h2 = fmaxf(p0*ca_w1[6] + p1*ca_w1[7] + p2*ca_w1[8], 0.f);
        #pragma unroll
        for (int k = 0; k < 3; k++) {
            float z = h0*ca_w2[k*3] + h1*ca_w2[k*3+1] + h2*ca_w2[k*3+2];
            g_scale[b*3+k] = 1.0f / (1.0f + expf(-z));
        }
        g_invmx[b] = 1.0f / (float)g_maxcode[b];
    }
}

// ---------------- K3: 7x7 conv -> sigmoid mask + block strength ------------
// block (32,8), 32x32 output tile, grid (16,16,B)
__global__ void k_mask(const float* __restrict__ frame,
                       const float* __restrict__ sa_w,
                       const float* __restrict__ sa_b,
                       float* __restrict__ maskout) {
    __shared__ float gs[4][38][38];
    __shared__ float wsm[4][7][7];
    __shared__ float msm[32][32];
    __shared__ float s_bias;
    const int b = blockIdx.z;
    const int tx = threadIdx.x, ty = threadIdx.y;
    const int tid = ty*32 + tx;
    if (tid < 196) ((float*)wsm)[tid] = sa_w[tid];
    if (tid == 196) s_bias = sa_b[0];
    const float invmx = g_invmx[b];
    const float* fr = frame + (size_t)b*3*HW;
    const unsigned char* cp = g_code + (size_t)b*HW;
    const int x0 = blockIdx.x*32 - 3, y0 = blockIdx.y*32 - 3;

    for (int i = tid; i < 38*38; i += 256) {
        int sy = i / 38, sx = i % 38;
        int y = y0 + sy, x = x0 + sx;
        bool in = (y >= 0) && (y < Hn) && (x >= 0) && (x < Wn);
        int o = y*Wn + x;
        gs[0][sy][sx] = in ? fr[o]          : 0.f;
        gs[1][sy][sx] = in ? fr[HW+o]       : 0.f;
        gs[2][sy][sx] = in ? fr[2*HW+o]     : 0.f;
        gs[3][sy][sx] = in ? (float)cp[o]*invmx : 0.f;
    }
    __syncthreads();

    float acc0 = s_bias, acc1 = s_bias, acc2 = s_bias, acc3 = s_bias;
    #pragma unroll
    for (int c = 0; c < 4; c++)
        #pragma unroll
        for (int ky = 0; ky < 7; ky++)
            #pragma unroll
            for (int kx = 0; kx < 7; kx++) {
                float wv = wsm[c][ky][kx];
                acc0 = fmaf(gs[c][ty     + ky][tx+kx], wv, acc0);
                acc1 = fmaf(gs[c][ty + 8 + ky][tx+kx], wv, acc1);
                acc2 = fmaf(gs[c][ty +16 + ky][tx+kx], wv, acc2);
                acc3 = fmaf(gs[c][ty +24 + ky][tx+kx], wv, acc3);
            }

    float mk[4] = { 1.f/(1.f+expf(-acc0)), 1.f/(1.f+expf(-acc1)),
                    1.f/(1.f+expf(-acc2)), 1.f/(1.f+expf(-acc3)) };
    #pragma unroll
    for (int k = 0; k < 4; k++) {
        int ry = ty + 8*k;
        msm[ry][tx] = mk[k];
        int gy = blockIdx.y*32 + ry, gx = blockIdx.x*32 + tx;
        maskout[(size_t)b*HW + gy*Wn + gx] = mk[k];
    }
    __syncthreads();
    if (tid < 16) {
        int sby = tid >> 2, sbx = tid & 3;
        float sum = 0.f;
        #pragma unroll
        for (int iy = 0; iy < 8; iy++)
            #pragma unroll
            for (int ix = 0; ix < 8; ix++)
                sum += msm[sby*8+iy][sbx*8+ix];
        g_strength[b*NBLK*NBLK + (blockIdx.y*4+sby)*NBLK + (blockIdx.x*4+sbx)] = sum * (1.f/64.f);
    }
}

// ---------------- K4: pointwise YUV + analytic DCT watermark + RGB ---------
// block (32,8), grid (4, 64, B); each thread handles 4 consecutive x pixels
__global__ void k_final(const float* __restrict__ frame,
                        const int* __restrict__ wm, int L,
                        float* __restrict__ out) {
    const int b = blockIdx.z;
    const int x = (blockIdx.x*32 + threadIdx.x) * 4;
    const int y = blockIdx.y*8 + threadIdx.y;
    const int go = (y*Wn + x) >> 2;
    const float4* fr = (const float4*)(frame + (size_t)b*3*HW);
    float4 r4 = fr[go], g4 = fr[(HW>>2)+go], b4 = fr[(2*HW>>2)+go];

    const float s0 = g_scale[b*3], s1 = g_scale[b*3+1], s2 = g_scale[b*3+2];
    const int by = y >> 3, bx = x >> 3;
    const float st = g_strength[b*NBLK*NBLK + by*NBLK + bx];
    const int widx = (by*NBLK + bx) % L;
    const float delta = 0.05f * st * (2.f*(float)wm[widx] - 1.f);
    const float ddi = delta * c_d4[y & 7];
    const int l0 = x & 7;  // 0 or 4; all 4 pixels stay in one 8-col block

    float ro[4], go4[4], bo[4];
    const float* rp = (const float*)&r4;
    const float* gp = (const float*)&g4;
    const float* bp = (const float*)&b4;
    #pragma unroll
    for (int j = 0; j < 4; j++) {
        float rr = rp[j], gg = gp[j], bb = bp[j];
        float yv =  0.299f*rr + 0.587f*gg + 0.114f*bb;
        float uu = -0.147f*rr - 0.289f*gg + 0.436f*bb;
        float vv =  0.615f*rr - 0.515f*gg - 0.100f*bb;
        float yw = yv*s0 + ddi*c_d3[l0 + j];
        float uw = uu*s1, vw = vv*s2;
        ro[j]  = yw + 1.14f*vw;
        go4[j] = yw - 0.395f*uw - 0.581f*vw;
        bo[j]  = yw + 2.032f*uw;
    }
    float4* po = (float4*)(out + (size_t)b*3*HW);
    po[go]            = make_float4(ro[0],  ro[1],  ro[2],  ro[3]);
    po[(HW>>2)+go]    = make_float4(go4[0], go4[1], go4[2], go4[3]);
    po[(2*HW>>2)+go]  = make_float4(bo[0],  bo[1],  bo[2],  bo[3]);
}

// ---------------- launch ----------------------------------------------------
extern "C" void kernel_launch(void* const* d_in, const int* in_sizes, int n_in,
                              void* d_out, int out_size) {
    const float* frame = (const float*)d_in[0];
    const int*   wm    = (const int*)d_in[1];
    const float* sa_w  = (const float*)d_in[2];
    const float* sa_b  = (const float*)d_in[3];
    const float* ca_w1 = (const float*)d_in[4];
    const float* ca_w2 = (const float*)d_in[5];
    const int L = in_sizes[1];
    float* out = (float*)d_out;
    float* maskout = out + (size_t)Bn*3*HW;

    k_init<<<1, 32>>>();
    k_lbp<<<dim3(16, 64, Bn), dim3(32, 8)>>>(frame);
    k_scale<<<Bn, 256>>>(ca_w1, ca_w2);
    k_mask<<<dim3(16, 16, Bn), dim3(32, 8)>>>(frame, sa_w, sa_b, maskout);
    k_final<<<dim3(4, 64, Bn), dim3(32, 8)>>>(frame, wm, L, out);
}

// round 2
// speedup vs baseline: 1.5288x; 1.5288x over previous
#include <cuda_runtime.h>
#include <math.h>

#define Bn 16
#define Hn 512
#define Wn 512
#define HW (Hn*Wn)
#define NBLK 64             // 512/8 blocks per dim
#define BLKS_PER_IMG 256    // K1: (512/32)*(512/32)

// ---------------- scratch (device globals; no allocation allowed) ----------
__device__ unsigned char g_code[(size_t)Bn*HW];     // LBP code 0..9
__device__ float g_partial[Bn*BLKS_PER_IMG*3];      // per-block rgb sums
__device__ int   g_maxcode[Bn];
__device__ float g_scale[Bn*3];
__device__ float g_invmx[Bn];
__device__ float g_strength[Bn*NBLK*NBLK];

// DCT basis rows 4 and 3 (orthonormal DCT-II)
__constant__ float c_d4[8] = { 0.35355339f,-0.35355339f,-0.35355339f, 0.35355339f,
                               0.35355339f,-0.35355339f,-0.35355339f, 0.35355339f };
__constant__ float c_d3[8] = { 0.41573481f,-0.09754516f,-0.49039264f,-0.27778512f,
                               0.27778512f, 0.49039264f, 0.09754516f,-0.41573481f };

// ---- packed f32x2 helpers (sm_100+) ---------------------------------------
__device__ __forceinline__ unsigned long long pk2(float lo, float hi) {
    unsigned long long d;
    asm("mov.b64 %0, {%1, %2};" : "=l"(d) : "f"(lo), "f"(hi));
    return d;
}
__device__ __forceinline__ unsigned long long ffma2(unsigned long long a,
                                                    unsigned long long b,
                                                    unsigned long long c) {
    unsigned long long d;
    asm("fma.rn.f32x2 %0, %1, %2, %3;" : "=l"(d) : "l"(a), "l"(b), "l"(c));
    return d;
}
__device__ __forceinline__ void unpk2(unsigned long long v, float& lo, float& hi) {
    asm("mov.b64 {%0, %1}, %2;" : "=f"(lo), "=f"(hi) : "l"(v));
}

__global__ void k_init() {
    if (threadIdx.x < Bn) g_maxcode[threadIdx.x] = 0;
}

// ---------------- K1: gray + LBP + rgb partial sums + code max -------------
// block (32,8), 32x32 tile, grid (16, 16, B); each thread 4 rows (stride 8)
__global__ void k_lbp(const float* __restrict__ frame) {
    __shared__ float gs[34][36];
    const int b = blockIdx.z;
    const float* fr = frame + (size_t)b*3*HW;
    const int bx0 = blockIdx.x*32, by0 = blockIdx.y*32;
    const int tx = threadIdx.x, ty = threadIdx.y;
    const int tid = ty*32 + tx;

    for (int i = tid; i < 34*34; i += 256) {
        int sy = i / 34, sx = i % 34;
        int y = min(max(by0 + sy - 1, 0), Hn-1);
        int x = min(max(bx0 + sx - 1, 0), Wn-1);
        int o = y*Wn + x;
        gs[sy][sx] = 0.299f*fr[o] + 0.587f*fr[HW+o] + 0.114f*fr[2*HW+o];
    }
    __syncthreads();

    const int x = bx0 + tx;
    float r = 0.f, g = 0.f, bl = 0.f;
    int m = 0;
    #pragma unroll
    for (int k = 0; k < 4; k++) {
        const int ry = ty + 8*k;
        const int y = by0 + ry;
        const float g0 = gs[ry+1][tx+1];
        int bb0 = gs[ry  ][tx+1] >= g0;
        int bb1 = gs[ry  ][tx+2] >= g0;
        int bb2 = gs[ry+1][tx+2] >= g0;
        int bb3 = gs[ry+2][tx+2] >= g0;
        int bb4 = gs[ry+2][tx+1] >= g0;
        int bb5 = gs[ry+2][tx  ] >= g0;
        int bb6 = gs[ry+1][tx  ] >= g0;
        int bb7 = gs[ry  ][tx  ] >= g0;
        int s = bb0+bb1+bb2+bb3+bb4+bb5+bb6+bb7;
        int trans = abs(bb0-bb7)+abs(bb1-bb0)+abs(bb2-bb1)+abs(bb3-bb2)
                  + abs(bb4-bb3)+abs(bb5-bb4)+abs(bb6-bb5)+abs(bb7-bb6);
        int code = (trans <= 2) ? s : 9;
        g_code[(size_t)b*HW + y*Wn + x] = (unsigned char)code;
        m = max(m, code);
        int o = y*Wn + x;
        r += fr[o]; g += fr[HW+o]; bl += fr[2*HW+o];
    }

    #pragma unroll
    for (int off = 16; off; off >>= 1) {
        r  += __shfl_down_sync(0xffffffffu, r,  off);
        g  += __shfl_down_sync(0xffffffffu, g,  off);
        bl += __shfl_down_sync(0xffffffffu, bl, off);
        m = max(m, __shfl_down_sync(0xffffffffu, m, off));
    }
    __shared__ float rs[3][8];
    __shared__ int ms[8];
    int lane = tid & 31, warp = tid >> 5;
    if (lane == 0) { rs[0][warp] = r; rs[1][warp] = g; rs[2][warp] = bl; ms[warp] = m; }
    __syncthreads();
    if (tid == 0) {
        float R=0, G=0, Bs=0; int mm = 0;
        #pragma unroll
        for (int w = 0; w < 8; w++) { R += rs[0][w]; G += rs[1][w]; Bs += rs[2][w]; mm = max(mm, ms[w]); }
        int gbid = b*BLKS_PER_IMG + blockIdx.y*16 + blockIdx.x;
        g_partial[gbid*3+0] = R;
        g_partial[gbid*3+1] = G;
        g_partial[gbid*3+2] = Bs;
        atomicMax(&g_maxcode[b], mm);
    }
}

// ---------------- K2: channel attention scale + 1/max ----------------------
__global__ void k_scale(const float* __restrict__ ca_w1, const float* __restrict__ ca_w2) {
    const int b = blockIdx.x;
    const int t = threadIdx.x;
    float r = 0.f, g = 0.f, bl = 0.f;
    if (t < BLKS_PER_IMG) {
        int o = (b*BLKS_PER_IMG + t)*3;
        r = g_partial[o]; g = g_partial[o+1]; bl = g_partial[o+2];
    }
    __shared__ float sm[3][256];
    sm[0][t] = r; sm[1][t] = g; sm[2][t] = bl;
    __syncthreads();
    for (int off = 128; off; off >>= 1) {
        if (t < off) { sm[0][t] += sm[0][t+off]; sm[1][t] += sm[1][t+off]; sm[2][t] += sm[2][t+off]; }
        __syncthreads();
    }
    if (t == 0) {
        const float inv = 1.0f / (float)HW;
        float rm = sm[0][0]*inv, gm = sm[1][0]*inv, bm = sm[2][0]*inv;
        float p0 =  0.299f*rm + 0.587f*gm + 0.114f*bm;
        float p1 = -0.147f*rm - 0.289f*gm + 0.436f*bm;
        float p2 =  0.615f*rm - 0.515f*gm - 0.100f*bm;
        float h0 = fmaxf(p0*ca_w1[0] + p1*ca_w1[1] + p2*ca_w1[2], 0.f);
        float h1 = fmaxf(p0*ca_w1[3] + p1*ca_w1[4] + p2*ca_w1[5], 0.f);
        float h2 = fmaxf(p0*ca_w1[6] + p1*ca_w1[7] + p2*ca_w1[8], 0.f);
        #pragma unroll
        for (int k = 0; k < 3; k++) {
            float z = h0*ca_w2[k*3] + h1*ca_w2[k*3+1] + h2*ca_w2[k*3+2];
            g_scale[b*3+k] = 1.0f / (1.0f + expf(-z));
        }
        g_invmx[b] = 1.0f / (float)g_maxcode[b];
    }
}

// ---------------- K3: 7x7 conv -> sigmoid mask + block strength ------------
// block (8,32): tx handles 4 consecutive x, ty = row. 32x32 out tile,
// grid (16,16,B). Data path: float4 LDS + packed f32x2 FMA.
__global__ void __launch_bounds__(256) k_mask(const float* __restrict__ frame,
                       const float* __restrict__ sa_w,
                       const float* __restrict__ sa_b,
                       float* __restrict__ maskout) {
    __shared__ float gs[4][38][40];
    __shared__ float wsm[4][7][8];
    __shared__ float msm[32][36];
    __shared__ float s_bias;
    const int b = blockIdx.z;
    const int tx = threadIdx.x, ty = threadIdx.y;   // tx 0..7, ty 0..31
    const int tid = ty*8 + tx;
    if (tid < 196) {
        int c = tid / 49, rem = tid % 49;
        wsm[c][rem/7][rem%7] = sa_w[tid];
    }
    if (tid == 196) s_bias = sa_b[0];
    const float invmx = g_invmx[b];
    const float* fr = frame + (size_t)b*3*HW;
    const unsigned char* cp = g_code + (size_t)b*HW;
    const int x0 = blockIdx.x*32 - 3, y0 = blockIdx.y*32 - 3;

    for (int i = tid; i < 38*38; i += 256) {
        int sy = i / 38, sx = i % 38;
        int y = y0 + sy, x = x0 + sx;
        bool in = (y >= 0) && (y < Hn) && (x >= 0) && (x < Wn);
        int o = y*Wn + x;
        gs[0][sy][sx] = in ? fr[o]          : 0.f;
        gs[1][sy][sx] = in ? fr[HW+o]       : 0.f;
        gs[2][sy][sx] = in ? fr[2*HW+o]     : 0.f;
        gs[3][sy][sx] = in ? (float)cp[o]*invmx : 0.f;
    }
    __syncthreads();

    const int x4 = tx*4;
    unsigned long long acc01 = pk2(s_bias, s_bias);
    unsigned long long acc23 = acc01;

    #pragma unroll
    for (int c = 0; c < 4; c++) {
        #pragma unroll
        for (int ky = 0; ky < 7; ky++) {
            const float* row = &gs[c][ty + ky][x4];
            float4 A = *(const float4*)(row);
            float4 Bv = *(const float4*)(row + 4);
            float4 Cv = *(const float4*)(row + 8);
            float d0=A.x, d1=A.y, d2=A.z, d3=A.w;
            float d4=Bv.x, d5=Bv.y, d6=Bv.z, d7=Bv.w;
            float d8=Cv.x, d9=Cv.y;
            float4 W0 = *(const float4*)&wsm[c][ky][0];
            float4 W1 = *(const float4*)&wsm[c][ky][4];
            unsigned long long w;
            w = pk2(W0.x, W0.x);
            acc01 = ffma2(pk2(d0, d1), w, acc01);
            acc23 = ffma2(pk2(d2, d3), w, acc23);
            w = pk2(W0.y, W0.y);
            acc01 = ffma2(pk2(d1, d2), w, acc01);
            acc23 = ffma2(pk2(d3, d4), w, acc23);
            w = pk2(W0.z, W0.z);
            acc01 = ffma2(pk2(d2, d3), w, acc01);
            acc23 = ffma2(pk2(d4, d5), w, acc23);
            w = pk2(W0.w, W0.w);
            acc01 = ffma2(pk2(d3, d4), w, acc01);
            acc23 = ffma2(pk2(d5, d6), w, acc23);
            w = pk2(W1.x, W1.x);
            acc01 = ffma2(pk2(d4, d5), w, acc01);
            acc23 = ffma2(pk2(d6, d7), w, acc23);
            w = pk2(W1.y, W1.y);
            acc01 = ffma2(pk2(d5, d6), w, acc01);
            acc23 = ffma2(pk2(d7, d8), w, acc23);
            w = pk2(W1.z, W1.z);
            acc01 = ffma2(pk2(d6, d7), w, acc01);
            acc23 = ffma2(pk2(d8, d9), w, acc23);
        }
    }

    float a0, a1, a2, a3;
    unpk2(acc01, a0, a1);
    unpk2(acc23, a2, a3);
    float m0 = 1.f/(1.f+expf(-a0)), m1 = 1.f/(1.f+expf(-a1));
    float m2 = 1.f/(1.f+expf(-a2)), m3 = 1.f/(1.f+expf(-a3));

    msm[ty][x4+0] = m0; msm[ty][x4+1] = m1;
    msm[ty][x4+2] = m2; msm[ty][x4+3] = m3;
    const int gy = blockIdx.y*32 + ty, gx = blockIdx.x*32 + x4;
    *(float4*)&maskout[(size_t)b*HW + gy*Wn + gx] = make_float4(m0, m1, m2, m3);

    __syncthreads();
    if (tid < 16) {
        int sby = tid >> 2, sbx = tid & 3;
        float sum = 0.f;
        #pragma unroll
        for (int iy = 0; iy < 8; iy++)
            #pragma unroll
            for (int ix = 0; ix < 8; ix++)
                sum += msm[sby*8+iy][sbx*8+ix];
        g_strength[b*NBLK*NBLK + (blockIdx.y*4+sby)*NBLK + (blockIdx.x*4+sbx)] = sum * (1.f/64.f);
    }
}

// ---------------- K4: pointwise YUV + analytic DCT watermark + RGB ---------
__global__ void k_final(const float* __restrict__ frame,
                        const int* __restrict__ wm, int L,
                        float* __restrict__ out) {
    const int b = blockIdx.z;
    const int x = (blockIdx.x*32 + threadIdx.x) * 4;
    const int y = blockIdx.y*8 + threadIdx.y;
    const int go = (y*Wn + x) >> 2;
    const float4* fr = (const float4*)(frame + (size_t)b*3*HW);
    float4 r4 = fr[go], g4 = fr[(HW>>2)+go], b4 = fr[(2*HW>>2)+go];

    const float s0 = g_scale[b*3], s1 = g_scale[b*3+1], s2 = g_scale[b*3+2];
    const int by = y >> 3, bx = x >> 3;
    const float st = g_strength[b*NBLK*NBLK + by*NBLK + bx];
    const int widx = (by*NBLK + bx) % L;
    const float delta = 0.05f * st * (2.f*(float)wm[widx] - 1.f);
    const float ddi = delta * c_d4[y & 7];
    const int l0 = x & 7;

    float ro[4], go4[4], bo[4];
    const float* rp = (const float*)&r4;
    const float* gp = (const float*)&g4;
    const float* bp = (const float*)&b4;
    #pragma unroll
    for (int j = 0; j < 4; j++) {
        float rr = rp[j], gg = gp[j], bb = bp[j];
        float yv =  0.299f*rr + 0.587f*gg + 0.114f*bb;
        float uu = -0.147f*rr - 0.289f*gg + 0.436f*bb;
        float vv =  0.615f*rr - 0.515f*gg - 0.100f*bb;
        float yw = yv*s0 + ddi*c_d3[l0 + j];
        float uw = uu*s1, vw = vv*s2;
        ro[j]  = yw + 1.14f*vw;
        go4[j] = yw - 0.395f*uw - 0.581f*vw;
        bo[j]  = yw + 2.032f*uw;
    }
    float4* po = (float4*)(out + (size_t)b*3*HW);
    po[go]            = make_float4(ro[0],  ro[1],  ro[2],  ro[3]);
    po[(HW>>2)+go]    = make_float4(go4[0], go4[1], go4[2], go4[3]);
    po[(2*HW>>2)+go]  = make_float4(bo[0],  bo[1],  bo[2],  bo[3]);
}

// ---------------- launch ----------------------------------------------------
extern "C" void kernel_launch(void* const* d_in, const int* in_sizes, int n_in,
                              void* d_out, int out_size) {
    const float* frame = (const float*)d_in[0];
    const int*   wm    = (const int*)d_in[1];
    const float* sa_w  = (const float*)d_in[2];
    const float* sa_b  = (const float*)d_in[3];
    const float* ca_w1 = (const float*)d_in[4];
    const float* ca_w2 = (const float*)d_in[5];
    const int L = in_sizes[1];
    float* out = (float*)d_out;
    float* maskout = out + (size_t)Bn*3*HW;

    k_init<<<1, 32>>>();
    k_lbp<<<dim3(16, 16, Bn), dim3(32, 8)>>>(frame);
    k_scale<<<Bn, 256>>>(ca_w1, ca_w2);
    k_mask<<<dim3(16, 16, Bn), dim3(8, 32)>>>(frame, sa_w, sa_b, maskout);
    k_final<<<dim3(4, 64, Bn), dim3(32, 8)>>>(frame, wm, L, out);
}

// round 3
// speedup vs baseline: 1.8045x; 1.1803x over previous
#include <cuda_runtime.h>
#include <math.h>

#define Bn 16
#define Hn 512
#define Wn 512
#define HW (Hn*Wn)
#define NBLK 64
#define BLKS_PER_IMG 256    // k_lbp: (512/32)^2

// ---------------- scratch ----------------
__device__ unsigned char g_code[(size_t)Bn*HW];
__device__ float g_partial[Bn*BLKS_PER_IMG*4];   // r,g,b,maxcode per 32x32 block
__device__ float g_scale[Bn*3];
__device__ float g_invmx[Bn];

__constant__ float c_d4[8] = { 0.35355339f,-0.35355339f,-0.35355339f, 0.35355339f,
                               0.35355339f,-0.35355339f,-0.35355339f, 0.35355339f };
__constant__ float c_d3[8] = { 0.41573481f,-0.09754516f,-0.49039264f,-0.27778512f,
                               0.27778512f, 0.49039264f, 0.09754516f,-0.41573481f };

// ---- packed f32x2 helpers ----
__device__ __forceinline__ unsigned long long pk2(float lo, float hi) {
    unsigned long long d;
    asm("mov.b64 %0, {%1, %2};" : "=l"(d) : "f"(lo), "f"(hi));
    return d;
}
__device__ __forceinline__ unsigned long long ffma2(unsigned long long a,
                                                    unsigned long long b,
                                                    unsigned long long c) {
    unsigned long long d;
    asm("fma.rn.f32x2 %0, %1, %2, %3;" : "=l"(d) : "l"(a), "l"(b), "l"(c));
    return d;
}
__device__ __forceinline__ void unpk2(unsigned long long v, float& lo, float& hi) {
    asm("mov.b64 {%0, %1}, %2;" : "=f"(lo), "=f"(hi) : "l"(v));
}

// ---------------- K1: gray + LBP + per-block rgb sums & code max -----------
// block (32,8), 32x32 tile, grid (16,16,B)
__global__ void k_lbp(const float* __restrict__ frame) {
    __shared__ float gs[34][36];
    const int b = blockIdx.z;
    const float* fr = frame + (size_t)b*3*HW;
    const int bx0 = blockIdx.x*32, by0 = blockIdx.y*32;
    const int tx = threadIdx.x, ty = threadIdx.y;
    const int tid = ty*32 + tx;

    for (int i = tid; i < 34*34; i += 256) {
        int sy = i / 34, sx = i % 34;
        int y = min(max(by0 + sy - 1, 0), Hn-1);
        int x = min(max(bx0 + sx - 1, 0), Wn-1);
        int o = y*Wn + x;
        gs[sy][sx] = 0.299f*fr[o] + 0.587f*fr[HW+o] + 0.114f*fr[2*HW+o];
    }
    __syncthreads();

    const int x = bx0 + tx;
    float r = 0.f, g = 0.f, bl = 0.f;
    int m = 0;
    #pragma unroll
    for (int k = 0; k < 4; k++) {
        const int ry = ty + 8*k;
        const int y = by0 + ry;
        const float g0 = gs[ry+1][tx+1];
        int bb0 = gs[ry  ][tx+1] >= g0;
        int bb1 = gs[ry  ][tx+2] >= g0;
        int bb2 = gs[ry+1][tx+2] >= g0;
        int bb3 = gs[ry+2][tx+2] >= g0;
        int bb4 = gs[ry+2][tx+1] >= g0;
        int bb5 = gs[ry+2][tx  ] >= g0;
        int bb6 = gs[ry+1][tx  ] >= g0;
        int bb7 = gs[ry  ][tx  ] >= g0;
        int s = bb0+bb1+bb2+bb3+bb4+bb5+bb6+bb7;
        int trans = abs(bb0-bb7)+abs(bb1-bb0)+abs(bb2-bb1)+abs(bb3-bb2)
                  + abs(bb4-bb3)+abs(bb5-bb4)+abs(bb6-bb5)+abs(bb7-bb6);
        int code = (trans <= 2) ? s : 9;
        g_code[(size_t)b*HW + y*Wn + x] = (unsigned char)code;
        m = max(m, code);
        int o = y*Wn + x;
        r += fr[o]; g += fr[HW+o]; bl += fr[2*HW+o];
    }

    #pragma unroll
    for (int off = 16; off; off >>= 1) {
        r  += __shfl_down_sync(0xffffffffu, r,  off);
        g  += __shfl_down_sync(0xffffffffu, g,  off);
        bl += __shfl_down_sync(0xffffffffu, bl, off);
        m = max(m, __shfl_down_sync(0xffffffffu, m, off));
    }
    __shared__ float rs[3][8];
    __shared__ int ms[8];
    int lane = tid & 31, warp = tid >> 5;
    if (lane == 0) { rs[0][warp] = r; rs[1][warp] = g; rs[2][warp] = bl; ms[warp] = m; }
    __syncthreads();
    if (tid == 0) {
        float R=0, G=0, Bs=0; int mm = 0;
        #pragma unroll
        for (int w = 0; w < 8; w++) { R += rs[0][w]; G += rs[1][w]; Bs += rs[2][w]; mm = max(mm, ms[w]); }
        int gbid = b*BLKS_PER_IMG + blockIdx.y*16 + blockIdx.x;
        g_partial[gbid*4+0] = R;
        g_partial[gbid*4+1] = G;
        g_partial[gbid*4+2] = Bs;
        g_partial[gbid*4+3] = (float)mm;
    }
}

// ---------------- K2: channel attention scale + 1/max ----------------------
__global__ void k_scale(const float* __restrict__ ca_w1, const float* __restrict__ ca_w2) {
    const int b = blockIdx.x;
    const int t = threadIdx.x;
    float4 v = make_float4(0.f, 0.f, 0.f, 0.f);
    if (t < BLKS_PER_IMG) v = *(const float4*)&g_partial[(b*BLKS_PER_IMG + t)*4];
    __shared__ float sm[4][256];
    sm[0][t] = v.x; sm[1][t] = v.y; sm[2][t] = v.z; sm[3][t] = v.w;
    __syncthreads();
    for (int off = 128; off; off >>= 1) {
        if (t < off) {
            sm[0][t] += sm[0][t+off]; sm[1][t] += sm[1][t+off];
            sm[2][t] += sm[2][t+off]; sm[3][t] = fmaxf(sm[3][t], sm[3][t+off]);
        }
        __syncthreads();
    }
    if (t == 0) {
        const float inv = 1.0f / (float)HW;
        float rm = sm[0][0]*inv, gm = sm[1][0]*inv, bm = sm[2][0]*inv;
        float p0 =  0.299f*rm + 0.587f*gm + 0.114f*bm;
        float p1 = -0.147f*rm - 0.289f*gm + 0.436f*bm;
        float p2 =  0.615f*rm - 0.515f*gm - 0.100f*bm;
        float h0 = fmaxf(p0*ca_w1[0] + p1*ca_w1[1] + p2*ca_w1[2], 0.f);
        float h1 = fmaxf(p0*ca_w1[3] + p1*ca_w1[4] + p2*ca_w1[5], 0.f);
        float h2 = fmaxf(p0*ca_w1[6] + p1*ca_w1[7] + p2*ca_w1[8], 0.f);
        #pragma unroll
        for (int k = 0; k < 3; k++) {
            float z = h0*ca_w2[k*3] + h1*ca_w2[k*3+1] + h2*ca_w2[k*3+2];
            g_scale[b*3+k] = 1.0f / (1.0f + expf(-z));
        }
        g_invmx[b] = 1.0f / sm[3][0];
    }
}

// ---------------- K3 (fused): conv7x7 -> mask + strength + watermark + RGB -
// Tile 64x32, block (16,8)=128 thr, each thread 4x4 outputs.
// Even/odd pair decomposition: zero data repacks, f32x2 throughout.
__global__ void __launch_bounds__(128) k_mask(const float* __restrict__ frame,
                       const float* __restrict__ sa_w,
                       const float* __restrict__ sa_b,
                       const int* __restrict__ wm, int L,
                       float* __restrict__ out,
                       float* __restrict__ maskout) {
    __shared__ float gs[4][38][72];                 // 43.8 kB
    __shared__ unsigned long long wp[4][7][8];      // We[4], Wo[4] per (c,ky)
    __shared__ float s_bias;
    const int b = blockIdx.z;
    const int tx = threadIdx.x, ty = threadIdx.y;   // tx 0..15, ty 0..7
    const int tid = ty*16 + tx;

    if (tid < 28) {
        int c = tid / 7, ky = tid % 7;
        const float* w = sa_w + c*49 + ky*7;
        float w0=w[0], w1=w[1], w2=w[2], w3=w[3], w4=w[4], w5=w[5], w6=w[6];
        wp[c][ky][0] = pk2(w0, w1);
        wp[c][ky][1] = pk2(w2, w3);
        wp[c][ky][2] = pk2(w4, w5);
        wp[c][ky][3] = pk2(w6, 0.f);
        wp[c][ky][4] = pk2(0.f, w0);
        wp[c][ky][5] = pk2(w1, w2);
        wp[c][ky][6] = pk2(w3, w4);
        wp[c][ky][7] = pk2(w5, w6);
    }
    if (tid == 28) s_bias = sa_b[0];

    const float invmx = g_invmx[b];
    const float* fr = frame + (size_t)b*3*HW;
    const unsigned char* cp = g_code + (size_t)b*HW;
    const int x0 = blockIdx.x*64 - 3, y0 = blockIdx.y*32 - 3;

    for (int i = tid; i < 38*70; i += 128) {
        int sy = i / 70, sx = i % 70;
        int y = y0 + sy, x = x0 + sx;
        bool in = (y >= 0) && (y < Hn) && (x >= 0) && (x < Wn);
        int o = y*Wn + x;
        gs[0][sy][sx] = in ? fr[o]              : 0.f;
        gs[1][sy][sx] = in ? fr[HW+o]           : 0.f;
        gs[2][sy][sx] = in ? fr[2*HW+o]         : 0.f;
        gs[3][sy][sx] = in ? (float)cp[o]*invmx : 0.f;
    }
    __syncthreads();

    const int x4  = tx*4;   // output col base within tile
    const int ry0 = ty*4;   // output row base within tile

    unsigned long long acc[4][4];
    {
        unsigned long long binit = pk2(s_bias, 0.f);
        #pragma unroll
        for (int o = 0; o < 4; o++)
            #pragma unroll
            for (int j = 0; j < 4; j++) acc[o][j] = binit;
    }

    #pragma unroll 1
    for (int c = 0; c < 4; c++) {
        #pragma unroll
        for (int rr = 0; rr < 10; rr++) {
            const float* row = &gs[c][ry0 + rr][x4];
            ulonglong2 p01 = *(const ulonglong2*)row;
            ulonglong2 p23 = *(const ulonglong2*)(row + 4);
            unsigned long long P4 = *(const unsigned long long*)(row + 8);
            unsigned long long P0 = p01.x, P1 = p01.y, P2 = p23.x, P3 = p23.y;
            #pragma unroll
            for (int ky = 0; ky < 7; ky++) {
                const int o = rr - ky;
                if (o < 0 || o > 3) continue;
                ulonglong2 we01 = *(const ulonglong2*)&wp[c][ky][0];
                ulonglong2 we23 = *(const ulonglong2*)&wp[c][ky][2];
                ulonglong2 wo01 = *(const ulonglong2*)&wp[c][ky][4];
                ulonglong2 wo23 = *(const ulonglong2*)&wp[c][ky][6];
                acc[o][0] = ffma2(P0, we01.x, ffma2(P1, we01.y,
                            ffma2(P2, we23.x, ffma2(P3, we23.y, acc[o][0]))));
                acc[o][1] = ffma2(P0, wo01.x, ffma2(P1, wo01.y,
                            ffma2(P2, wo23.x, ffma2(P3, wo23.y, acc[o][1]))));
                acc[o][2] = ffma2(P1, we01.x, ffma2(P2, we01.y,
                            ffma2(P3, we23.x, ffma2(P4, we23.y, acc[o][2]))));
                acc[o][3] = ffma2(P1, wo01.x, ffma2(P2, wo01.y,
                            ffma2(P3, wo23.x, ffma2(P4, wo23.y, acc[o][3]))));
            }
        }
    }

    // sigmoid + block strength (8x8 blocks = 2x2 threads; partners in-warp)
    float mval[4][4];
    float sum16 = 0.f;
    #pragma unroll
    for (int o = 0; o < 4; o++)
        #pragma unroll
        for (int j = 0; j < 4; j++) {
            float lo, hi; unpk2(acc[o][j], lo, hi);
            float m = 1.f/(1.f + __expf(-(lo + hi)));
            mval[o][j] = m;
            sum16 += m;
        }
    sum16 += __shfl_xor_sync(0xffffffffu, sum16, 1);   // tx pair
    sum16 += __shfl_xor_sync(0xffffffffu, sum16, 16);  // ty pair
    const float st = sum16 * (1.f/64.f);

    const int gx0 = blockIdx.x*64 + x4;
    const int gy0 = blockIdx.y*32 + ry0;
    const int bxb = gx0 >> 3, byb = gy0 >> 3;
    const int widx = (byb*NBLK + bxb) % L;
    const float delta = 0.05f * st * (2.f*(float)wm[widx] - 1.f);
    const float s0 = g_scale[b*3], s1 = g_scale[b*3+1], s2 = g_scale[b*3+2];
    const int l0 = gx0 & 7;
    float d3v0 = c_d3[l0], d3v1 = c_d3[l0+1], d3v2 = c_d3[l0+2], d3v3 = c_d3[l0+3];

    float* outp = out + (size_t)b*3*HW;
    float* mp   = maskout + (size_t)b*HW;
    #pragma unroll
    for (int o = 0; o < 4; o++) {
        const int gy = gy0 + o;
        const int sy = ry0 + o + 3;
        const float ddi = delta * c_d4[gy & 7];
        float ro[4], go[4], bo[4];
        #pragma unroll
        for (int j = 0; j < 4; j++) {
            float rr = gs[0][sy][x4+3+j];
            float gg = gs[1][sy][x4+3+j];
            float bb = gs[2][sy][x4+3+j];
            float yv =  0.299f*rr + 0.587f*gg + 0.114f*bb;
            float uu = -0.147f*rr - 0.289f*gg + 0.436f*bb;
            float vv =  0.615f*rr - 0.515f*gg - 0.100f*bb;
            float d3j = (j==0)?d3v0:(j==1)?d3v1:(j==2)?d3v2:d3v3;
            float yw = yv*s0 + ddi*d3j;
            float uw = uu*s1, vw = vv*s2;
            ro[j] = yw + 1.14f*vw;
            go[j] = yw - 0.395f*uw - 0.581f*vw;
            bo[j] = yw + 2.032f*uw;
        }
        size_t ob = (size_t)gy*Wn + gx0;
        *(float4*)&outp[ob]        = make_float4(ro[0], ro[1], ro[2], ro[3]);
        *(float4*)&outp[HW + ob]   = make_float4(go[0], go[1], go[2], go[3]);
        *(float4*)&outp[2*HW + ob] = make_float4(bo[0], bo[1], bo[2], bo[3]);
        *(float4*)&mp[ob] = make_float4(mval[o][0], mval[o][1], mval[o][2], mval[o][3]);
    }
}

// ---------------- launch ----------------------------------------------------
extern "C" void kernel_launch(void* const* d_in, const int* in_sizes, int n_in,
                              void* d_out, int out_size) {
    const float* frame = (const float*)d_in[0];
    const int*   wm    = (const int*)d_in[1];
    const float* sa_w  = (const float*)d_in[2];
    const float* sa_b  = (const float*)d_in[3];
    const float* ca_w1 = (const float*)d_in[4];
    const float* ca_w2 = (const float*)d_in[5];
    const int L = in_sizes[1];
    float* out = (float*)d_out;
    float* maskout = out + (size_t)Bn*3*HW;

    k_lbp<<<dim3(16, 16, Bn), dim3(32, 8)>>>(frame);
    k_scale<<<Bn, 256>>>(ca_w1, ca_w2);
    k_mask<<<dim3(8, 16, Bn), dim3(16, 8)>>>(frame, sa_w, sa_b, wm, L, out, maskout);
}

// round 5
// speedup vs baseline: 2.2840x; 1.2657x over previous
#include <cuda_runtime.h>
#include <math.h>

#define Bn 16
#define Hn 512
#define Wn 512
#define HW (Hn*Wn)
#define NBLK 64
#define BLKS_PER_IMG 128    // k_lbp: (512/64)*(512/32)

// ---------------- scratch ----------------
__device__ unsigned char g_code[(size_t)Bn*HW];
__device__ float g_partial[Bn*BLKS_PER_IMG*4];   // r,g,b,maxcode per 64x32 tile
__device__ float g_scale[Bn*3];
__device__ float g_invmx[Bn];
__device__ unsigned long long g_wpad[225];       // staging for constant weights

__constant__ unsigned long long c_wp[225];       // [ (c*7+ky)*8 + j ], [224]=bias pair
__constant__ float c_d4[8] = { 0.35355339f,-0.35355339f,-0.35355339f, 0.35355339f,
                               0.35355339f,-0.35355339f,-0.35355339f, 0.35355339f };
__constant__ float c_d3[8] = { 0.41573481f,-0.09754516f,-0.49039264f,-0.27778512f,
                               0.27778512f, 0.49039264f, 0.09754516f,-0.41573481f };

// ---- packed f32x2 helpers ----
__device__ __forceinline__ unsigned long long pk2(float lo, float hi) {
    unsigned long long d;
    asm("mov.b64 %0, {%1, %2};" : "=l"(d) : "f"(lo), "f"(hi));
    return d;
}
__device__ __forceinline__ unsigned long long ffma2(unsigned long long a,
                                                    unsigned long long b,
                                                    unsigned long long c) {
    unsigned long long d;
    asm("fma.rn.f32x2 %0, %1, %2, %3;" : "=l"(d) : "l"(a), "l"(b), "l"(c));
    return d;
}
__device__ __forceinline__ void unpk2(unsigned long long v, float& lo, float& hi) {
    asm("mov.b64 {%0, %1}, %2;" : "=f"(lo), "=f"(hi) : "l"(v));
}

// ---------------- K1: gray + LBP(popc) + per-tile rgb sums & code max ------
// flat 256 threads, 64x32 tile, grid (8,16,B)
__global__ void __launch_bounds__(256) k_lbp(const float* __restrict__ frame) {
    __shared__ float gs[34][72];    // smem col of rel-x X is X+4; halo col 3 / 68
    __shared__ float rs[4][8];
    const int b = blockIdx.z;
    const float* fr = frame + (size_t)b*3*HW;
    const int bx0 = blockIdx.x*64, by0 = blockIdx.y*32;
    const int tid = threadIdx.x;

    float sr = 0.f, sg = 0.f, sb = 0.f;
    #pragma unroll
    for (int k = 0; k < 2; k++) {
        int q = tid + k*256;
        int qy = q >> 4, qx = q & 15;
        int o = (by0+qy)*Wn + bx0 + qx*4;
        float4 r  = *(const float4*)(fr + o);
        float4 g  = *(const float4*)(fr + HW + o);
        float4 bl = *(const float4*)(fr + 2*HW + o);
        float4 gr;
        gr.x = 0.299f*r.x + 0.587f*g.x + 0.114f*bl.x;
        gr.y = 0.299f*r.y + 0.587f*g.y + 0.114f*bl.y;
        gr.z = 0.299f*r.z + 0.587f*g.z + 0.114f*bl.z;
        gr.w = 0.299f*r.w + 0.587f*g.w + 0.114f*bl.w;
        *(float4*)&gs[qy+1][qx*4+4] = gr;
        sr += r.x+r.y+r.z+r.w;
        sg += g.x+g.y+g.z+g.w;
        sb += bl.x+bl.y+bl.z+bl.w;
    }
    // halo (edge clamp)
    if (tid < 196) {
        int gx, gy, sy, sx;
        if (tid < 66)       { gy = max(by0-1, 0);      gx = min(max(bx0-1+tid, 0), Wn-1);      sy = 0;        sx = 3+tid; }
        else if (tid < 132) { gy = min(by0+32, Hn-1);  gx = min(max(bx0-1+(tid-66), 0), Wn-1); sy = 33;       sx = 3+(tid-66); }
        else if (tid < 164) { int j = tid-132; gy = by0+j; gx = max(bx0-1, 0);                 sy = j+1;      sx = 3; }
        else                { int j = tid-164; gy = by0+j; gx = min(bx0+64, Wn-1);             sy = j+1;      sx = 68; }
        int o = gy*Wn + gx;
        gs[sy][sx] = 0.299f*fr[o] + 0.587f*fr[HW+o] + 0.114f*fr[2*HW+o];
    }
    __syncthreads();

    int cmax = 0;
    #pragma unroll
    for (int k = 0; k < 2; k++) {
        int q = tid + k*256;
        int qy = q >> 4, qx = q & 15;
        int ry = qy + 1, P = qx*4;
        float4 A0 = *(const float4*)&gs[ry-1][P];
        float4 A1 = *(const float4*)&gs[ry-1][P+4];
        float  a8 = gs[ry-1][P+8];
        float4 B0 = *(const float4*)&gs[ry  ][P];
        float4 B1 = *(const float4*)&gs[ry  ][P+4];
        float  b8 = gs[ry  ][P+8];
        float4 C0 = *(const float4*)&gs[ry+1][P];
        float4 C1 = *(const float4*)&gs[ry+1][P+4];
        float  c8 = gs[ry+1][P+8];
        float av[9] = {A0.x,A0.y,A0.z,A0.w,A1.x,A1.y,A1.z,A1.w,a8};
        float bv[9] = {B0.x,B0.y,B0.z,B0.w,B1.x,B1.y,B1.z,B1.w,b8};
        float cv[9] = {C0.x,C0.y,C0.z,C0.w,C1.x,C1.y,C1.z,C1.w,c8};
        unsigned int codes = 0;
        #pragma unroll
        for (int p = 0; p < 4; p++) {
            float g0 = bv[4+p];
            int m = (int)(av[4+p] >= g0)
                  | ((int)(av[5+p] >= g0) << 1)
                  | ((int)(bv[5+p] >= g0) << 2)
                  | ((int)(cv[5+p] >= g0) << 3)
                  | ((int)(cv[4+p] >= g0) << 4)
                  | ((int)(cv[3+p] >= g0) << 5)
                  | ((int)(bv[3+p] >= g0) << 6)
                  | ((int)(av[3+p] >= g0) << 7);
            int rot = ((m << 1) | (m >> 7)) & 255;
            int trans = __popc(m ^ rot);
            int s = __popc(m);
            int code = (trans <= 2) ? s : 9;
            cmax = max(cmax, code);
            codes |= ((unsigned int)code) << (8*p);
        }
        *(unsigned int*)&g_code[(size_t)b*HW + (by0+qy)*Wn + bx0 + P] = codes;
    }

    #pragma unroll
    for (int off = 16; off; off >>= 1) {
        sr += __shfl_down_sync(0xffffffffu, sr, off);
        sg += __shfl_down_sync(0xffffffffu, sg, off);
        sb += __shfl_down_sync(0xffffffffu, sb, off);
        cmax = max(cmax, __shfl_down_sync(0xffffffffu, cmax, off));
    }
    int lane = tid & 31, warp = tid >> 5;
    if (lane == 0) { rs[0][warp] = sr; rs[1][warp] = sg; rs[2][warp] = sb; rs[3][warp] = (float)cmax; }
    __syncthreads();
    if (tid == 0) {
        float R=0, G=0, Bs=0, M=0;
        #pragma unroll
        for (int w = 0; w < 8; w++) { R += rs[0][w]; G += rs[1][w]; Bs += rs[2][w]; M = fmaxf(M, rs[3][w]); }
        int gbid = b*BLKS_PER_IMG + blockIdx.y*8 + blockIdx.x;
        g_partial[gbid*4+0] = R;
        g_partial[gbid*4+1] = G;
        g_partial[gbid*4+2] = Bs;
        g_partial[gbid*4+3] = M;
    }
}

// ---------------- K2: channel attention scale + 1/max + weight-pair build --
__global__ void k_scale(const float* __restrict__ ca_w1, const float* __restrict__ ca_w2,
                        const float* __restrict__ sa_w, const float* __restrict__ sa_b) {
    const int b = blockIdx.x;
    const int t = threadIdx.x;

    if (b == 0) {   // build padded weight-pair table for k_mask
        if (t < 28) {
            int c = t / 7, ky = t % 7;
            const float* w = sa_w + c*49 + ky*7;
            float w0=w[0], w1=w[1], w2=w[2], w3=w[3], w4=w[4], w5=w[5], w6=w[6];
            unsigned long long* d = &g_wpad[(c*7+ky)*8];
            d[0] = pk2(w0, w1); d[1] = pk2(w2, w3);
            d[2] = pk2(w4, w5); d[3] = pk2(w6, 0.f);
            d[4] = pk2(0.f, w0); d[5] = pk2(w1, w2);
            d[6] = pk2(w3, w4); d[7] = pk2(w5, w6);
        } else if (t == 28) {
            g_wpad[224] = pk2(sa_b[0], 0.f);
        }
    }

    float4 v = *(const float4*)&g_partial[(b*BLKS_PER_IMG + t)*4];
    __shared__ float sm[4][128];
    sm[0][t] = v.x; sm[1][t] = v.y; sm[2][t] = v.z; sm[3][t] = v.w;
    __syncthreads();
    for (int off = 64; off; off >>= 1) {
        if (t < off) {
            sm[0][t] += sm[0][t+off]; sm[1][t] += sm[1][t+off];
            sm[2][t] += sm[2][t+off]; sm[3][t] = fmaxf(sm[3][t], sm[3][t+off]);
        }
        __syncthreads();
    }
    if (t == 0) {
        const float inv = 1.0f / (float)HW;
        float rm = sm[0][0]*inv, gm = sm[1][0]*inv, bm = sm[2][0]*inv;
        float p0 =  0.299f*rm + 0.587f*gm + 0.114f*bm;
        float p1 = -0.147f*rm - 0.289f*gm + 0.436f*bm;
        float p2 =  0.615f*rm - 0.515f*gm - 0.100f*bm;
        float h0 = fmaxf(p0*ca_w1[0] + p1*ca_w1[1] + p2*ca_w1[2], 0.f);
        float h1 = fmaxf(p0*ca_w1[3] + p1*ca_w1[4] + p2*ca_w1[5], 0.f);
        float h2 = fmaxf(p0*ca_w1[6] + p1*ca_w1[7] + p2*ca_w1[8], 0.f);
        #pragma unroll
        for (int k = 0; k < 3; k++) {
            float z = h0*ca_w2[k*3] + h1*ca_w2[k*3+1] + h2*ca_w2[k*3+2];
            g_scale[b*3+k] = 1.0f / (1.0f + expf(-z));
        }
        g_invmx[b] = 1.0f / sm[3][0];
    }
}

// ---------------- K3 (fused): conv7x7 + mask + strength + watermark + RGB --
// Tile 64x32, block (16,8)=128 thr, thread = 4x4 outputs. Weights via constant.
__global__ void __launch_bounds__(128) k_mask(const float* __restrict__ frame,
                       const int* __restrict__ wm, int L,
                       float* __restrict__ out,
                       float* __restrict__ maskout) {
    __shared__ float gs[4][38][72];
    const int b = blockIdx.z;
    const int tx = threadIdx.x, ty = threadIdx.y;   // tx 0..15, ty 0..7
    const int tid = ty*16 + tx;

    const float invmx = g_invmx[b];
    const float* fr = frame + (size_t)b*3*HW;
    const unsigned char* cp = g_code + (size_t)b*HW;
    const int x0 = blockIdx.x*64 - 3, y0 = blockIdx.y*32 - 3;

    for (int i = tid; i < 38*70; i += 128) {
        int sy = i / 70, sx = i % 70;
        int y = y0 + sy, x = x0 + sx;
        bool in = (y >= 0) && (y < Hn) && (x >= 0) && (x < Wn);
        int o = y*Wn + x;
        gs[0][sy][sx] = in ? fr[o]              : 0.f;
        gs[1][sy][sx] = in ? fr[HW+o]           : 0.f;
        gs[2][sy][sx] = in ? fr[2*HW+o]         : 0.f;
        gs[3][sy][sx] = in ? (float)cp[o]*invmx : 0.f;
    }
    __syncthreads();

    const int x4  = tx*4;
    const int ry0 = ty*4;

    unsigned long long acc[4][4];
    {
        unsigned long long binit = c_wp[224];
        #pragma unroll
        for (int o = 0; o < 4; o++)
            #pragma unroll
            for (int j = 0; j < 4; j++) acc[o][j] = binit;
    }

    #pragma unroll 1
    for (int c = 0; c < 4; c++) {
        #pragma unroll
        for (int rr = 0; rr < 10; rr++) {
            const float* row = &gs[c][ry0 + rr][x4];
            ulonglong2 p01 = *(const ulonglong2*)row;
            ulonglong2 p23 = *(const ulonglong2*)(row + 4);
            unsigned long long P4 = *(const unsigned long long*)(row + 8);
            unsigned long long P0 = p01.x, P1 = p01.y, P2 = p23.x, P3 = p23.y;
            #pragma unroll
            for (int ky = 0; ky < 7; ky++) {
                const int o = rr - ky;
                if (o < 0 || o > 3) continue;
                const unsigned long long* W = &c_wp[(c*7 + ky)*8];
                acc[o][0] = ffma2(P0, W[0], ffma2(P1, W[1],
                            ffma2(P2, W[2], ffma2(P3, W[3], acc[o][0]))));
                acc[o][1] = ffma2(P0, W[4], ffma2(P1, W[5],
                            ffma2(P2, W[6], ffma2(P3, W[7], acc[o][1]))));
                acc[o][2] = ffma2(P1, W[0], ffma2(P2, W[1],
                            ffma2(P3, W[2], ffma2(P4, W[3], acc[o][2]))));
                acc[o][3] = ffma2(P1, W[4], ffma2(P2, W[5],
                            ffma2(P3, W[6], ffma2(P4, W[7], acc[o][3]))));
            }
        }
    }

    float mval[4][4];
    float sum16 = 0.f;
    #pragma unroll
    for (int o = 0; o < 4; o++)
        #pragma unroll
        for (int j = 0; j < 4; j++) {
            float lo, hi; unpk2(acc[o][j], lo, hi);
            float m = 1.f/(1.f + __expf(-(lo + hi)));
            mval[o][j] = m;
            sum16 += m;
        }
    sum16 += __shfl_xor_sync(0xffffffffu, sum16, 1);
    sum16 += __shfl_xor_sync(0xffffffffu, sum16, 16);
    const float st = sum16 * (1.f/64.f);

    const int gx0 = blockIdx.x*64 + x4;
    const int gy0 = blockIdx.y*32 + ry0;
    const int bxb = gx0 >> 3, byb = gy0 >> 3;
    const int widx = (byb*NBLK + bxb) % L;
    const float delta = 0.05f * st * (2.f*(float)wm[widx] - 1.f);
    const float s0 = g_scale[b*3], s1 = g_scale[b*3+1], s2 = g_scale[b*3+2];
    const int l0 = gx0 & 7;
    float d3v0 = c_d3[l0], d3v1 = c_d3[l0+1], d3v2 = c_d3[l0+2], d3v3 = c_d3[l0+3];

    float* outp = out + (size_t)b*3*HW;
    float* mp   = maskout + (size_t)b*HW;
    #pragma unroll
    for (int o = 0; o < 4; o++) {
        const int gy = gy0 + o;
        const int sy = ry0 + o + 3;
        const float ddi = delta * c_d4[gy & 7];
        float ro[4], go[4], bo[4];
        #pragma unroll
        for (int j = 0; j < 4; j++) {
            float rr = gs[0][sy][x4+3+j];
            float gg = gs[1][sy][x4+3+j];
            float bb = gs[2][sy][x4+3+j];
            float yv =  0.299f*rr + 0.587f*gg + 0.114f*bb;
            float uu = -0.147f*rr - 0.289f*gg + 0.436f*bb;
            float vv =  0.615f*rr - 0.515f*gg - 0.100f*bb;
            float d3j = (j==0)?d3v0:(j==1)?d3v1:(j==2)?d3v2:d3v3;
            float yw = yv*s0 + ddi*d3j;
            float uw = uu*s1, vw = vv*s2;
            ro[j] = yw + 1.14f*vw;
            go[j] = yw - 0.395f*uw - 0.581f*vw;
            bo[j] = yw + 2.032f*uw;
        }
        size_t ob = (size_t)gy*Wn + gx0;
        *(float4*)&outp[ob]        = make_float4(ro[0], ro[1], ro[2], ro[3]);
        *(float4*)&outp[HW + ob]   = make_float4(go[0], go[1], go[2], go[3]);
        *(float4*)&outp[2*HW + ob] = make_float4(bo[0], bo[1], bo[2], bo[3]);
        *(float4*)&mp[ob] = make_float4(mval[o][0], mval[o][1], mval[o][2], mval[o][3]);
    }
}

// ---------------- launch ----------------------------------------------------
extern "C" void kernel_launch(void* const* d_in, const int* in_sizes, int n_in,
                              void* d_out, int out_size) {
    const float* frame = (const float*)d_in[0];
    const int*   wm    = (const int*)d_in[1];
    const float* sa_w  = (const float*)d_in[2];
    const float* sa_b  = (const float*)d_in[3];
    const float* ca_w1 = (const float*)d_in[4];
    const float* ca_w2 = (const float*)d_in[5];
    const int L = in_sizes[1];
    float* out = (float*)d_out;
    float* maskout = out + (size_t)Bn*3*HW;

    k_lbp<<<dim3(8, 16, Bn), 256>>>(frame);
    k_scale<<<Bn, 128>>>(ca_w1, ca_w2, sa_w, sa_b);

    void* src = nullptr;
    cudaGetSymbolAddress(&src, g_wpad);
    cudaMemcpyToSymbolAsync(c_wp, src, 225*sizeof(unsigned long long), 0,
                            cudaMemcpyDeviceToDevice, 0);

    k_mask<<<dim3(8, 16, Bn), dim3(16, 8)>>>(frame, wm, L, out, maskout);
}

// round 6
// speedup vs baseline: 2.3984x; 1.0501x over previous
#include <cuda_runtime.h>
#include <math.h>

#define Bn 16
#define Hn 512
#define Wn 512
#define HW (Hn*Wn)
#define NBLK 64
#define BLKS_PER_IMG 128    // k_lbp: (512/64)*(512/32)

// ---------------- scratch ----------------
__device__ unsigned char g_code[(size_t)Bn*HW];
__device__ float g_partial[Bn*BLKS_PER_IMG*4];   // r,g,b,maxcode per 64x32 tile
__device__ float g_scale[Bn*3];
__device__ float g_invmx[Bn];
__device__ unsigned long long g_wpad[225];       // staging for constant weights

__constant__ unsigned long long c_wp[225];       // [(c*7+ky)*8 + j], [224]=bias
__constant__ float c_d4[8] = { 0.35355339f,-0.35355339f,-0.35355339f, 0.35355339f,
                               0.35355339f,-0.35355339f,-0.35355339f, 0.35355339f };
__constant__ float c_d3[8] = { 0.41573481f,-0.09754516f,-0.49039264f,-0.27778512f,
                               0.27778512f, 0.49039264f, 0.09754516f,-0.41573481f };

// ---- packed f32x2 helpers ----
__device__ __forceinline__ unsigned long long pk2(float lo, float hi) {
    unsigned long long d;
    asm("mov.b64 %0, {%1, %2};" : "=l"(d) : "f"(lo), "f"(hi));
    return d;
}
__device__ __forceinline__ unsigned long long ffma2(unsigned long long a,
                                                    unsigned long long b,
                                                    unsigned long long c) {
    unsigned long long d;
    asm("fma.rn.f32x2 %0, %1, %2, %3;" : "=l"(d) : "l"(a), "l"(b), "l"(c));
    return d;
}
__device__ __forceinline__ void unpk2(unsigned long long v, float& lo, float& hi) {
    asm("mov.b64 {%0, %1}, %2;" : "=f"(lo), "=f"(hi) : "l"(v));
}

// ---------------- K1: gray + LBP(popc) + per-tile rgb sums & code max ------
// 256 threads, 64x32 tile, grid (8,16,B). smem col c <-> x = bx*64-4+c.
__global__ void __launch_bounds__(256) k_lbp(const float* __restrict__ frame) {
    __shared__ float gs[34][72];
    __shared__ float rs[4][8];
    const int b = blockIdx.z;
    const float* fr = frame + (size_t)b*3*HW;
    const int Bx = blockIdx.x*64, by0 = blockIdx.y*32;
    const int tid = threadIdx.x;

    float sr = 0.f, sg = 0.f, sb = 0.f;
    // fill: 34 rows x 18 float4 slots, edge-clamped
    #pragma unroll
    for (int k = 0; k < 3; k++) {
        int i = tid + k*256;
        if (i < 34*18) {
            int r = i / 18, ci = i % 18;
            int y = min(max(by0 - 1 + r, 0), Hn-1);
            int xb = Bx - 4 + ci*4;
            float4 rv, gv, bv;
            if (xb >= 0 && xb <= Wn-4) {
                int o = y*Wn + xb;
                rv = *(const float4*)(fr + o);
                gv = *(const float4*)(fr + HW + o);
                bv = *(const float4*)(fr + 2*HW + o);
            } else {
                float* rp = (float*)&rv; float* gp = (float*)&gv; float* bp = (float*)&bv;
                #pragma unroll
                for (int j = 0; j < 4; j++) {
                    int x = min(max(xb + j, 0), Wn-1);
                    int o = y*Wn + x;
                    rp[j] = fr[o]; gp[j] = fr[HW+o]; bp[j] = fr[2*HW+o];
                }
            }
            float4 gr;
            gr.x = 0.299f*rv.x + 0.587f*gv.x + 0.114f*bv.x;
            gr.y = 0.299f*rv.y + 0.587f*gv.y + 0.114f*bv.y;
            gr.z = 0.299f*rv.z + 0.587f*gv.z + 0.114f*bv.z;
            gr.w = 0.299f*rv.w + 0.587f*gv.w + 0.114f*bv.w;
            *(float4*)&gs[r][ci*4] = gr;
            if (r >= 1 && r <= 32 && ci >= 1 && ci <= 16) {
                sr += rv.x+rv.y+rv.z+rv.w;
                sg += gv.x+gv.y+gv.z+gv.w;
                sb += bv.x+bv.y+bv.z+bv.w;
            }
        }
    }
    __syncthreads();

    int cmax = 0;
    #pragma unroll
    for (int k = 0; k < 2; k++) {
        int q = tid + k*256;
        int qy = q >> 4, qx = q & 15;
        int ry = qy + 1, P = qx*4;
        float4 A0 = *(const float4*)&gs[ry-1][P];
        float4 A1 = *(const float4*)&gs[ry-1][P+4];
        float  a8 = gs[ry-1][P+8];
        float4 B0 = *(const float4*)&gs[ry  ][P];
        float4 B1 = *(const float4*)&gs[ry  ][P+4];
        float  b8 = gs[ry  ][P+8];
        float4 C0 = *(const float4*)&gs[ry+1][P];
        float4 C1 = *(const float4*)&gs[ry+1][P+4];
        float  c8 = gs[ry+1][P+8];
        float av[9] = {A0.x,A0.y,A0.z,A0.w,A1.x,A1.y,A1.z,A1.w,a8};
        float bv[9] = {B0.x,B0.y,B0.z,B0.w,B1.x,B1.y,B1.z,B1.w,b8};
        float cv[9] = {C0.x,C0.y,C0.z,C0.w,C1.x,C1.y,C1.z,C1.w,c8};
        unsigned int codes = 0;
        #pragma unroll
        for (int p = 0; p < 4; p++) {
            float g0 = bv[4+p];
            int m = (int)(av[4+p] >= g0)
                  | ((int)(av[5+p] >= g0) << 1)
                  | ((int)(bv[5+p] >= g0) << 2)
                  | ((int)(cv[5+p] >= g0) << 3)
                  | ((int)(cv[4+p] >= g0) << 4)
                  | ((int)(cv[3+p] >= g0) << 5)
                  | ((int)(bv[3+p] >= g0) << 6)
                  | ((int)(av[3+p] >= g0) << 7);
            int rot = ((m << 1) | (m >> 7)) & 255;
            int code = (__popc(m ^ rot) <= 2) ? __popc(m) : 9;
            cmax = max(cmax, code);
            codes |= ((unsigned int)code) << (8*p);
        }
        *(unsigned int*)&g_code[(size_t)b*HW + (by0+qy)*Wn + Bx + P] = codes;
    }

    #pragma unroll
    for (int off = 16; off; off >>= 1) {
        sr += __shfl_down_sync(0xffffffffu, sr, off);
        sg += __shfl_down_sync(0xffffffffu, sg, off);
        sb += __shfl_down_sync(0xffffffffu, sb, off);
        cmax = max(cmax, __shfl_down_sync(0xffffffffu, cmax, off));
    }
    int lane = tid & 31, warp = tid >> 5;
    if (lane == 0) { rs[0][warp] = sr; rs[1][warp] = sg; rs[2][warp] = sb; rs[3][warp] = (float)cmax; }
    __syncthreads();
    if (tid == 0) {
        float R=0, G=0, Bs=0, M=0;
        #pragma unroll
        for (int w = 0; w < 8; w++) { R += rs[0][w]; G += rs[1][w]; Bs += rs[2][w]; M = fmaxf(M, rs[3][w]); }
        int gbid = b*BLKS_PER_IMG + blockIdx.y*8 + blockIdx.x;
        g_partial[gbid*4+0] = R;
        g_partial[gbid*4+1] = G;
        g_partial[gbid*4+2] = Bs;
        g_partial[gbid*4+3] = M;
    }
}

// ---------------- K2: channel attention scale + 1/max + weight-pair build --
__global__ void k_scale(const float* __restrict__ ca_w1, const float* __restrict__ ca_w2,
                        const float* __restrict__ sa_w, const float* __restrict__ sa_b) {
    const int b = blockIdx.x;
    const int t = threadIdx.x;

    if (b == 0) {
        if (t < 28) {
            int c = t / 7, ky = t % 7;
            const float* w = sa_w + c*49 + ky*7;
            float w0=w[0], w1=w[1], w2=w[2], w3=w[3], w4=w[4], w5=w[5], w6=w[6];
            unsigned long long* d = &g_wpad[(c*7+ky)*8];
            d[0] = pk2(w0, w1); d[1] = pk2(w2, w3);
            d[2] = pk2(w4, w5); d[3] = pk2(w6, 0.f);
            d[4] = pk2(0.f, w0); d[5] = pk2(w1, w2);
            d[6] = pk2(w3, w4); d[7] = pk2(w5, w6);
        } else if (t == 28) {
            g_wpad[224] = pk2(sa_b[0], 0.f);
        }
    }

    float4 v = *(const float4*)&g_partial[(b*BLKS_PER_IMG + t)*4];
    __shared__ float sm[4][128];
    sm[0][t] = v.x; sm[1][t] = v.y; sm[2][t] = v.z; sm[3][t] = v.w;
    __syncthreads();
    for (int off = 64; off; off >>= 1) {
        if (t < off) {
            sm[0][t] += sm[0][t+off]; sm[1][t] += sm[1][t+off];
            sm[2][t] += sm[2][t+off]; sm[3][t] = fmaxf(sm[3][t], sm[3][t+off]);
        }
        __syncthreads();
    }
    if (t == 0) {
        const float inv = 1.0f / (float)HW;
        float rm = sm[0][0]*inv, gm = sm[1][0]*inv, bm = sm[2][0]*inv;
        float p0 =  0.299f*rm + 0.587f*gm + 0.114f*bm;
        float p1 = -0.147f*rm - 0.289f*gm + 0.436f*bm;
        float p2 =  0.615f*rm - 0.515f*gm - 0.100f*bm;
        float h0 = fmaxf(p0*ca_w1[0] + p1*ca_w1[1] + p2*ca_w1[2], 0.f);
        float h1 = fmaxf(p0*ca_w1[3] + p1*ca_w1[4] + p2*ca_w1[5], 0.f);
        float h2 = fmaxf(p0*ca_w1[6] + p1*ca_w1[7] + p2*ca_w1[8], 0.f);
        #pragma unroll
        for (int k = 0; k < 3; k++) {
            float z = h0*ca_w2[k*3] + h1*ca_w2[k*3+1] + h2*ca_w2[k*3+2];
            g_scale[b*3+k] = 1.0f / (1.0f + expf(-z));
        }
        g_invmx[b] = 1.0f / sm[3][0];
    }
}

// ---------------- K3 (fused): conv7x7 + mask + strength + watermark + RGB --
// Tile 64x32, block (16,8), thread = 4x4 outputs.
// smem col c <-> x = bx*64-4+c (16B-aligned); conv rows y0=by*32-3.
__global__ void __launch_bounds__(128) k_mask(const float* __restrict__ frame,
                       const int* __restrict__ wm, int L,
                       float* __restrict__ out,
                       float* __restrict__ maskout) {
    __shared__ float gs[4][38][72];     // 43.8 kB
    const int b = blockIdx.z;
    const int tx = threadIdx.x, ty = threadIdx.y;   // tx 0..15, ty 0..7
    const int tid = ty*16 + tx;

    const float invmx = g_invmx[b];
    const float* fr = frame + (size_t)b*3*HW;
    const unsigned char* cp = g_code + (size_t)b*HW;
    const int Bx = blockIdx.x*64;
    const int y0 = blockIdx.y*32 - 3;

    // vectorized fill: 38 rows x 18 float4 slots, zero-pad OOB
    #pragma unroll
    for (int k = 0; k < 6; k++) {
        int i = tid + k*128;
        if (i < 38*18) {
            int r = i / 18, ci = i % 18;
            int y = y0 + r;
            int xb = Bx - 4 + ci*4;
            bool yin = (unsigned)y < (unsigned)Hn;
            float4 rv, gv, bv, cv;
            if (yin && xb >= 0 && xb <= Wn-4) {
                int o = y*Wn + xb;
                rv = *(const float4*)(fr + o);
                gv = *(const float4*)(fr + HW + o);
                bv = *(const float4*)(fr + 2*HW + o);
                unsigned int cw = *(const unsigned int*)(cp + o);
                cv.x = (float)(cw & 255u)*invmx;
                cv.y = (float)((cw >> 8) & 255u)*invmx;
                cv.z = (float)((cw >> 16) & 255u)*invmx;
                cv.w = (float)(cw >> 24)*invmx;
            } else {
                float* rp = (float*)&rv; float* gp = (float*)&gv;
                float* bp = (float*)&bv; float* qp = (float*)&cv;
                #pragma unroll
                for (int j = 0; j < 4; j++) {
                    int x = xb + j;
                    bool in = yin && (unsigned)x < (unsigned)Wn;
                    int o = y*Wn + x;
                    rp[j] = in ? fr[o]              : 0.f;
                    gp[j] = in ? fr[HW+o]           : 0.f;
                    bp[j] = in ? fr[2*HW+o]         : 0.f;
                    qp[j] = in ? (float)cp[o]*invmx : 0.f;
                }
            }
            *(float4*)&gs[0][r][ci*4] = rv;
            *(float4*)&gs[1][r][ci*4] = gv;
            *(float4*)&gs[2][r][ci*4] = bv;
            *(float4*)&gs[3][r][ci*4] = cv;
        }
    }
    __syncthreads();

    const int x4  = tx*4;
    const int ry0 = ty*4;

    unsigned long long acc[4][4];
    {
        unsigned long long binit = c_wp[224];
        #pragma unroll
        for (int o = 0; o < 4; o++)
            #pragma unroll
            for (int j = 0; j < 4; j++) acc[o][j] = binit;
    }

    // window for output u starts at col u+1 (odd): j0/j2 use Wo, j1/j3 use We
    #pragma unroll 1
    for (int c = 0; c < 4; c++) {
        #pragma unroll
        for (int rr = 0; rr < 10; rr++) {
            const float* row = &gs[c][ry0 + rr][x4];
            ulonglong2 pA = *(const ulonglong2*)row;        // P0 P1
            ulonglong2 pB = *(const ulonglong2*)(row + 4);  // P2 P3
            ulonglong2 pC = *(const ulonglong2*)(row + 8);  // P4 P5
            unsigned long long P0 = pA.x, P1 = pA.y, P2 = pB.x,
                               P3 = pB.y, P4 = pC.x, P5 = pC.y;
            #pragma unroll
            for (int ky = 0; ky < 7; ky++) {
                const int o = rr - ky;
                if (o < 0 || o > 3) continue;
                const ulonglong2* Wp = (const ulonglong2*)&c_wp[(c*7 + ky)*8];
                ulonglong2 we01 = Wp[0];   // W0 W1
                ulonglong2 we23 = Wp[1];   // W2 W3
                ulonglong2 wo01 = Wp[2];   // W4 W5
                ulonglong2 wo23 = Wp[3];   // W6 W7
                acc[o][0] = ffma2(P0, wo01.x, ffma2(P1, wo01.y,
                            ffma2(P2, wo23.x, ffma2(P3, wo23.y, acc[o][0]))));
                acc[o][1] = ffma2(P1, we01.x, ffma2(P2, we01.y,
                            ffma2(P3, we23.x, ffma2(P4, we23.y, acc[o][1]))));
                acc[o][2] = ffma2(P1, wo01.x, ffma2(P2, wo01.y,
                            ffma2(P3, wo23.x, ffma2(P4, wo23.y, acc[o][2]))));
                acc[o][3] = ffma2(P2, we01.x, ffma2(P3, we01.y,
                            ffma2(P4, we23.x, ffma2(P5, we23.y, acc[o][3]))));
            }
        }
    }

    float mval[4][4];
    float sum16 = 0.f;
    #pragma unroll
    for (int o = 0; o < 4; o++)
        #pragma unroll
        for (int j = 0; j < 4; j++) {
            float lo, hi; unpk2(acc[o][j], lo, hi);
            float m = 1.f/(1.f + __expf(-(lo + hi)));
            mval[o][j] = m;
            sum16 += m;
        }
    sum16 += __shfl_xor_sync(0xffffffffu, sum16, 1);
    sum16 += __shfl_xor_sync(0xffffffffu, sum16, 16);
    const float st = sum16 * (1.f/64.f);

    const int gx0 = Bx + x4;
    const int gy0 = blockIdx.y*32 + ry0;
    const int bxb = gx0 >> 3, byb = gy0 >> 3;
    const int widx = (byb*NBLK + bxb) % L;
    const float delta = 0.05f * st * (2.f*(float)wm[widx] - 1.f);
    const float s0 = g_scale[b*3], s1 = g_scale[b*3+1], s2 = g_scale[b*3+2];
    const int l0 = gx0 & 7;
    float d3v0 = c_d3[l0], d3v1 = c_d3[l0+1], d3v2 = c_d3[l0+2], d3v3 = c_d3[l0+3];

    float* outp = out + (size_t)b*3*HW;
    float* mp   = maskout + (size_t)b*HW;
    #pragma unroll
    for (int o = 0; o < 4; o++) {
        const int gy = gy0 + o;
        const int sy = ry0 + o + 3;
        const float ddi = delta * c_d4[gy & 7];
        float ro[4], go[4], bo[4];
        #pragma unroll
        for (int j = 0; j < 4; j++) {
            float rr = gs[0][sy][x4+4+j];
            float gg = gs[1][sy][x4+4+j];
            float bb = gs[2][sy][x4+4+j];
            float yv =  0.299f*rr + 0.587f*gg + 0.114f*bb;
            float uu = -0.147f*rr - 0.289f*gg + 0.436f*bb;
            float vv =  0.615f*rr - 0.515f*gg - 0.100f*bb;
            float d3j = (j==0)?d3v0:(j==1)?d3v1:(j==2)?d3v2:d3v3;
            float yw = yv*s0 + ddi*d3j;
            float uw = uu*s1, vw = vv*s2;
            ro[j] = yw + 1.14f*vw;
            go[j] = yw - 0.395f*uw - 0.581f*vw;
            bo[j] = yw + 2.032f*uw;
        }
        size_t ob = (size_t)gy*Wn + gx0;
        *(float4*)&outp[ob]        = make_float4(ro[0], ro[1], ro[2], ro[3]);
        *(float4*)&outp[HW + ob]   = make_float4(go[0], go[1], go[2], go[3]);
        *(float4*)&outp[2*HW + ob] = make_float4(bo[0], bo[1], bo[2], bo[3]);
        *(float4*)&mp[ob] = make_float4(mval[o][0], mval[o][1], mval[o][2], mval[o][3]);
    }
}

// ---------------- launch ----------------------------------------------------
extern "C" void kernel_launch(void* const* d_in, const int* in_sizes, int n_in,
                              void* d_out, int out_size) {
    const float* frame = (const float*)d_in[0];
    const int*   wm    = (const int*)d_in[1];
    const float* sa_w  = (const float*)d_in[2];
    const float* sa_b  = (const float*)d_in[3];
    const float* ca_w1 = (const float*)d_in[4];
    const float* ca_w2 = (const float*)d_in[5];
    const int L = in_sizes[1];
    float* out = (float*)d_out;
    float* maskout = out + (size_t)Bn*3*HW;

    k_lbp<<<dim3(8, 16, Bn), 256>>>(frame);
    k_scale<<<Bn, 128>>>(ca_w1, ca_w2, sa_w, sa_b);

    void* src = nullptr;
    cudaGetSymbolAddress(&src, g_wpad);
    cudaMemcpyToSymbolAsync(c_wp, src, 225*sizeof(unsigned long long), 0,
                            cudaMemcpyDeviceToDevice, 0);

    k_mask<<<dim3(8, 16, Bn), dim3(16, 8)>>>(frame, wm, L, out, maskout);
}